// round 16
// baseline (speedup 1.0000x reference)
#include <cuda_runtime.h>
#include <cuda_bf16.h>
#include <cstdint>

// Problem constants: B=2, S=2048, H=1024, NH=16, d=64
#define B_    2
#define S_    2048
#define H_    1024
#define NH_   16
#define DH_   64
#define M_TOT 4096

// ---------------- static device scratch (allocation-free) ----------------
__device__ float          g_qkv [M_TOT * 3 * H_];   // tf32-rounded
__device__ __nv_bfloat16  g_hh  [M_TOT * H_];
__device__ __nv_bfloat16  g_hl  [M_TOT * H_];
__device__ __nv_bfloat16  g_wh  [3 * H_ * H_];
__device__ __nv_bfloat16  g_wl  [3 * H_ * H_];
__device__ __nv_bfloat16  g_ath [M_TOT * H_];
__device__ __nv_bfloat16  g_atl [M_TOT * H_];

// ---------------- helpers ----------------
static __device__ __forceinline__ uint32_t smem_u32(const void* p) {
    uint32_t a;
    asm("{ .reg .u64 t; cvta.to.shared.u64 t, %1; cvt.u32.u64 %0, t; }"
        : "=r"(a) : "l"(p));
    return a;
}
static __device__ __forceinline__ uint32_t tf32_bits(float x) {
    uint32_t r; asm("cvt.rna.tf32.f32 %0, %1;" : "=r"(r) : "f"(x)); return r;
}
static __device__ __forceinline__ float tf32_rna(float x) {
    return __uint_as_float(tf32_bits(x));
}
static __device__ __forceinline__ float ex2f(float x) {
    float r; asm("ex2.approx.f32 %0, %1;" : "=f"(r) : "f"(x)); return r;
}
static __device__ __forceinline__ uint32_t f2u(float x) { return __float_as_uint(x); }
static __device__ __forceinline__ uint32_t bfpack(__nv_bfloat16 a, __nv_bfloat16 b) {
    return (uint32_t)__bfloat16_as_ushort(a) |
           ((uint32_t)__bfloat16_as_ushort(b) << 16);
}

#define CP16(dst, src) \
    asm volatile("cp.async.cg.shared.global [%0], [%1], 16;" :: "r"(dst), "l"(src))
#define CP_COMMIT() asm volatile("cp.async.commit_group;" ::: "memory")
#define CP_WAIT1()  asm volatile("cp.async.wait_group 1;" ::: "memory")
#define CP_WAIT0()  asm volatile("cp.async.wait_group 0;" ::: "memory")

#define LDSM4(r, addr)                                                        \
    asm volatile("ldmatrix.sync.aligned.m8n8.x4.shared.b16 {%0,%1,%2,%3}, [%4];" \
        : "=r"((r)[0]), "=r"((r)[1]), "=r"((r)[2]), "=r"((r)[3]) : "r"(addr))

// m16n8k8 tf32 mma (attention)
static __device__ __forceinline__ void mma8(float* c, const uint32_t* a,
                                            const uint32_t* b) {
    asm volatile(
        "mma.sync.aligned.m16n8k8.row.col.f32.tf32.tf32.f32 "
        "{%0,%1,%2,%3},{%4,%5,%6,%7},{%8,%9},{%0,%1,%2,%3};"
        : "+f"(c[0]), "+f"(c[1]), "+f"(c[2]), "+f"(c[3])
        : "r"(a[0]), "r"(a[1]), "r"(a[2]), "r"(a[3]), "r"(b[0]), "r"(b[1]));
}
// m16n8k16 bf16 mma (dense GEMMs)
static __device__ __forceinline__ void mma16(float* c, const uint32_t* a,
                                             const uint32_t* b) {
    asm volatile(
        "mma.sync.aligned.m16n8k16.row.col.f32.bf16.bf16.f32 "
        "{%0,%1,%2,%3},{%4,%5,%6,%7},{%8,%9},{%0,%1,%2,%3};"
        : "+f"(c[0]), "+f"(c[1]), "+f"(c[2]), "+f"(c[3])
        : "r"(a[0]), "r"(a[1]), "r"(a[2]), "r"(a[3]), "r"(b[0]), "r"(b[1]));
}

// ---------------------------------------------------------------------------
// Pre-pass 1: fp32 -> bf16 hi/lo split
// ---------------------------------------------------------------------------
__global__ void split_bf16(const float4* __restrict__ x, uint2* __restrict__ hi,
                           uint2* __restrict__ lo, int n4)
{
    for (int i = blockIdx.x * blockDim.x + threadIdx.x; i < n4;
         i += gridDim.x * blockDim.x) {
        float4 v = x[i];
        __nv_bfloat16 h0 = __float2bfloat16_rn(v.x);
        __nv_bfloat16 h1 = __float2bfloat16_rn(v.y);
        __nv_bfloat16 h2 = __float2bfloat16_rn(v.z);
        __nv_bfloat16 h3 = __float2bfloat16_rn(v.w);
        __nv_bfloat16 l0 = __float2bfloat16_rn(v.x - __bfloat162float(h0));
        __nv_bfloat16 l1 = __float2bfloat16_rn(v.y - __bfloat162float(h1));
        __nv_bfloat16 l2 = __float2bfloat16_rn(v.z - __bfloat162float(h2));
        __nv_bfloat16 l3 = __float2bfloat16_rn(v.w - __bfloat162float(h3));
        hi[i] = make_uint2(bfpack(h0, h1), bfpack(h2, h3));
        lo[i] = make_uint2(bfpack(l0, l1), bfpack(l2, l3));
    }
}

// ---------------------------------------------------------------------------
// Pre-pass 2: W[K][N] -> W^T hi/lo [N][K] bf16 (transpose + split)
// ---------------------------------------------------------------------------
__global__ void tsplit_bf16(const float* __restrict__ W,
                            __nv_bfloat16* __restrict__ bth,
                            __nv_bfloat16* __restrict__ btl, int K, int N)
{
    __shared__ float t[32][33];
    const int tx = threadIdx.x, ty = threadIdx.y;
    const int n0 = blockIdx.x * 32, k0 = blockIdx.y * 32;
    #pragma unroll
    for (int i = 0; i < 4; i++)
        t[ty + i * 8][tx] = W[(size_t)(k0 + ty + i * 8) * N + n0 + tx];
    __syncthreads();
    #pragma unroll
    for (int i = 0; i < 4; i++) {
        float v = t[tx][ty + i * 8];
        __nv_bfloat16 h = __float2bfloat16_rn(v);
        __nv_bfloat16 l = __float2bfloat16_rn(v - __bfloat162float(h));
        size_t o = (size_t)(n0 + ty + i * 8) * K + k0 + tx;
        bth[o] = h; btl[o] = l;
    }
}

// ---------------------------------------------------------------------------
// bf16x3 GEMM: CTA 128x128, 256 threads / 8 warps (warp tile 32x64, grid
// 4m x 2n), K-stage 32, 2-stage cp.async ring (round-13 proven pipeline),
// ldmatrix.x4, term-grouped MMAs. occ 2 -> 16 warps/SM for latency hiding.
// ---------------------------------------------------------------------------
#define GBW     20                      // u32 words per row (16 data + 4 pad)
#define GBARR   (128 * GBW)             // words per matrix per stage
#define GBSTAGE (4 * GBARR)             // Ah, Al, Bh, Bl (40 KB)
#define GBSMEM_BYTES (2 * GBSTAGE * 4)  // 81920

template <int ROUND>
__global__ __launch_bounds__(256, 2)
void gemm_bf16x3(const __nv_bfloat16* __restrict__ Ah,
                 const __nv_bfloat16* __restrict__ Al,
                 const __nv_bfloat16* __restrict__ Bh,
                 const __nv_bfloat16* __restrict__ Bl,
                 float* __restrict__ C, int M, int N, int K)
{
    extern __shared__ uint32_t smw[];
    const uint32_t sbase = smem_u32(smw);
    const int tid = threadIdx.x, lane = tid & 31, wid = tid >> 5;
    const int g = lane >> 2, tig = lane & 3;
    const int wm = wid & 3, wn = wid >> 2;       // 4(m) x 2(n), warp 32x64
    const int m0 = blockIdx.y * 128, n0 = blockIdx.x * 128;
    const int nst = K / 32;

    float acc[2][8][4];
    #pragma unroll
    for (int i = 0; i < 2; i++)
        #pragma unroll
        for (int j = 0; j < 8; j++)
            #pragma unroll
            for (int q = 0; q < 4; q++) acc[i][j][q] = 0.f;

    auto issue = [&](int s) {
        const int buf = s & 1, k0 = s * 32;
        const uint32_t sb = sbase + buf * (GBSTAGE * 4);
        #pragma unroll
        for (int i = 0; i < 2; i++) {
            int l = i * 256 + tid;                // 512 16B-chunks per matrix
            int r = l >> 2, ch = l & 3;
            uint32_t off = (uint32_t)(r * GBW + ch * 4) * 4;
            size_t ga = (size_t)(m0 + r) * K + k0 + ch * 8;
            size_t gb = (size_t)(n0 + r) * K + k0 + ch * 8;
            CP16(sb + off,                 &Ah[ga]);
            CP16(sb + GBARR * 4 + off,     &Al[ga]);
            CP16(sb + 2 * GBARR * 4 + off, &Bh[gb]);
            CP16(sb + 3 * GBARR * 4 + off, &Bl[gb]);
        }
        CP_COMMIT();
    };
    issue(0); issue(1);

    // ldmatrix per-thread offsets (same fragment mapping as round 13)
    const int rowA = (lane & 7) + 8 * ((lane >> 3) & 1);
    const int kwA  = 4 * (lane >> 4);
    const int rowB = (lane & 7) + 8 * (lane >> 4);
    const int kwB  = 4 * ((lane >> 3) & 1);
    const uint32_t offA = (uint32_t)((wm * 32 + rowA) * GBW + kwA) * 4;
    const uint32_t offB = (uint32_t)((wn * 64 + rowB) * GBW + kwB) * 4;

    for (int s = 0; s < nst; s++) {
        if (s + 1 < nst) { CP_WAIT1(); } else { CP_WAIT0(); }
        __syncthreads();
        const uint32_t bb = sbase + (s & 1) * (GBSTAGE * 4);
        const uint32_t aH = bb + offA;
        const uint32_t aL = aH + GBARR * 4;
        const uint32_t bH = bb + 2 * GBARR * 4 + offB;
        const uint32_t bL = bH + GBARR * 4;

        #pragma unroll
        for (int s8 = 0; s8 < 2; s8++) {
            const uint32_t ks = (uint32_t)s8 * 32;      // k16 step = 8 words
            uint32_t ah[2][4], al[2][4];
            #pragma unroll
            for (int i = 0; i < 2; i++) {               // 2 m16 tiles (32 rows)
                LDSM4(ah[i], aH + (uint32_t)i * (16 * GBW * 4) + ks);
                LDSM4(al[i], aL + (uint32_t)i * (16 * GBW * 4) + ks);
            }
            #pragma unroll
            for (int jp = 0; jp < 4; jp++) {            // 4 n16 pairs (64 cols)
                uint32_t bh[4], bl[4];
                LDSM4(bh, bH + (uint32_t)jp * (16 * GBW * 4) + ks);
                LDSM4(bl, bL + (uint32_t)jp * (16 * GBW * 4) + ks);
                // term-grouped: each acc reused at distance 4 MMAs
                #pragma unroll
                for (int i = 0; i < 2; i++) {
                    mma16(acc[i][2 * jp],     ah[i], bh);
                    mma16(acc[i][2 * jp + 1], ah[i], bh + 2);
                }
                #pragma unroll
                for (int i = 0; i < 2; i++) {
                    mma16(acc[i][2 * jp],     ah[i], bl);
                    mma16(acc[i][2 * jp + 1], ah[i], bl + 2);
                }
                #pragma unroll
                for (int i = 0; i < 2; i++) {
                    mma16(acc[i][2 * jp],     al[i], bh);
                    mma16(acc[i][2 * jp + 1], al[i], bh + 2);
                }
            }
        }
        __syncthreads();
        if (s + 2 < nst) issue(s + 2);
    }

    #pragma unroll
    for (int i = 0; i < 2; i++) {
        int r0 = m0 + wm * 32 + i * 16 + g;
        #pragma unroll
        for (int j = 0; j < 8; j++) {
            int cn = n0 + wn * 64 + j * 8 + 2 * tig;
            float4 v = make_float4(acc[i][j][0], acc[i][j][1],
                                   acc[i][j][2], acc[i][j][3]);
            if (ROUND) {
                v.x = tf32_rna(v.x); v.y = tf32_rna(v.y);
                v.z = tf32_rna(v.z); v.w = tf32_rna(v.w);
            }
            *(float2*)&C[(size_t)r0 * N + cn] = make_float2(v.x, v.y);
            *(float2*)&C[(size_t)(r0 + 8) * N + cn] = make_float2(v.z, v.w);
        }
    }
}

// ---------------------------------------------------------------------------
// Flash attention (unchanged from rounds 14/15): software-pipelined
// S(kt+1)+PV(kt), 4-stage K/V ring, no-max softmax, Q in regs, 2 CTAs/SM.
// ---------------------------------------------------------------------------
#define AQ_STR 68
#define AK_STR 68
#define AV_STR 72
#define AP_STR 36
#define ASTAGE (32 * AK_STR + 32 * AV_STR)       // 4480 floats per ring stage
#define OFF_P  (4 * ASTAGE)                      // 17920
#define ATT_SMEM_FLOATS (OFF_P + 128 * AP_STR)   // 22528
#define ATT_SMEM_BYTES  (ATT_SMEM_FLOATS * 4)    // 90112

__global__ __launch_bounds__(128, 2)
void flash_attn_mma(const float* __restrict__ qkv,
                    __nv_bfloat16* __restrict__ out_hi,
                    __nv_bfloat16* __restrict__ out_lo,
                    const float* __restrict__ ssm_ptr)
{
    extern __shared__ float sm[];
    const uint32_t sbase = smem_u32(sm);
    const int tid = threadIdx.x, lane = tid & 31, wid = tid >> 5;
    const int g = lane >> 2, tig = lane & 3;
    const int qt = blockIdx.x, bh = blockIdx.y;
    const int b = bh >> 4, h = bh & 15;
    const int s0 = qt * 128;

    const float* qbase = qkv + (size_t)b * S_ * 3072 + h * 64;
    const float* kbase = qbase + 1024;
    const float* vbase = qbase + 2048;

    const int prow = 32 * wid + g;

    const float QSC = 0.125f * 1.4426950408889634f;
    #pragma unroll
    for (int it = 0; it < 16; it++) {
        int lin = it * 128 + tid;
        int r = lin >> 4, c = (lin & 15) * 4;
        float4 v = *(const float4*)&qbase[(size_t)(s0 + r) * 3072 + c];
        v.x = tf32_rna(v.x * QSC); v.y = tf32_rna(v.y * QSC);
        v.z = tf32_rna(v.z * QSC); v.w = tf32_rna(v.w * QSC);
        *(float4*)&sm[r * AQ_STR + c] = v;
    }
    __syncthreads();
    uint32_t qreg[2][8][4];
    #pragma unroll
    for (int t = 0; t < 2; t++) {
        const int rr = prow + 16 * t;
        #pragma unroll
        for (int k8 = 0; k8 < 8; k8++) {
            const int kc = k8 * 8;
            qreg[t][k8][0] = f2u(sm[rr * AQ_STR + kc + tig]);
            qreg[t][k8][1] = f2u(sm[(rr + 8) * AQ_STR + kc + tig]);
            qreg[t][k8][2] = f2u(sm[rr * AQ_STR + kc + tig + 4]);
            qreg[t][k8][3] = f2u(sm[(rr + 8) * AQ_STR + kc + tig + 4]);
        }
    }
    __syncthreads();

    auto issue_kv = [&](int kt) {
        const int buf = kt & 3, j0 = kt * 32;
        const uint32_t kdst = sbase + (uint32_t)(buf * ASTAGE) * 4;
        const uint32_t vdst = kdst + (uint32_t)(32 * AK_STR) * 4;
        #pragma unroll
        for (int i = 0; i < 4; i++) {
            int l = i * 128 + tid;
            int r = l >> 4, ch = (l & 15) * 4;
            CP16(kdst + (uint32_t)(r * AK_STR + ch) * 4,
                 &kbase[(size_t)(j0 + r) * 3072 + ch]);
            CP16(vdst + (uint32_t)(r * AV_STR + ch) * 4,
                 &vbase[(size_t)(j0 + r) * 3072 + ch]);
        }
        CP_COMMIT();
    };

    float lp[4] = {0.f, 0.f, 0.f, 0.f};
    float o[2][8][4];
    #pragma unroll
    for (int t = 0; t < 2; t++)
        #pragma unroll
        for (int j = 0; j < 8; j++)
            #pragma unroll
            for (int q = 0; q < 4; q++) o[t][j][q] = 0.f;

    auto s_tile = [&](float s[2][4][4], const float* Kb) {
        #pragma unroll
        for (int k8 = 0; k8 < 8; k8++) {
            const int kc = k8 * 8;
            #pragma unroll
            for (int j = 0; j < 4; j++) {
                uint32_t bb[2];
                bb[0] = f2u(Kb[(8 * j + g) * AK_STR + kc + tig]);
                bb[1] = f2u(Kb[(8 * j + g) * AK_STR + kc + tig + 4]);
                mma8(s[0][j], qreg[0][k8], bb);
                mma8(s[1][j], qreg[1][k8], bb);
            }
        }
    };
    auto soft_store = [&](float s[2][4][4]) {
        #pragma unroll
        for (int t = 0; t < 2; t++) {
            const int rr = prow + 16 * t;
            #pragma unroll
            for (int j = 0; j < 4; j++) {
                float p0 = ex2f(s[t][j][0]), p1 = ex2f(s[t][j][1]);
                float p2 = ex2f(s[t][j][2]), p3 = ex2f(s[t][j][3]);
                lp[2 * t]     += p0 + p1;
                lp[2 * t + 1] += p2 + p3;
                int cc = j * 8 + 2 * tig;
                *(float2*)&sm[OFF_P + rr * AP_STR + cc] =
                    make_float2(tf32_rna(p0), tf32_rna(p1));
                *(float2*)&sm[OFF_P + (rr + 8) * AP_STR + cc] =
                    make_float2(tf32_rna(p2), tf32_rna(p3));
            }
        }
        __syncwarp();
    };
    auto pv_tile = [&](const float* Vb) {
        #pragma unroll
        for (int k8 = 0; k8 < 4; k8++) {
            const int kc = k8 * 8;
            uint32_t pa[2][4];
            #pragma unroll
            for (int t = 0; t < 2; t++) {
                int rr = prow + 16 * t;
                pa[t][0] = f2u(sm[OFF_P + rr * AP_STR + kc + tig]);
                pa[t][1] = f2u(sm[OFF_P + (rr + 8) * AP_STR + kc + tig]);
                pa[t][2] = f2u(sm[OFF_P + rr * AP_STR + kc + tig + 4]);
                pa[t][3] = f2u(sm[OFF_P + (rr + 8) * AP_STR + kc + tig + 4]);
            }
            #pragma unroll
            for (int j = 0; j < 8; j++) {
                uint32_t bb[2];
                bb[0] = f2u(Vb[(kc + tig) * AV_STR + j * 8 + g]);
                bb[1] = f2u(Vb[(kc + tig + 4) * AV_STR + j * 8 + g]);
                mma8(o[0][j], pa[0], bb);
                mma8(o[1][j], pa[1], bb);
            }
        }
    };

    issue_kv(0); issue_kv(1);
    CP_WAIT1();
    __syncthreads();
    issue_kv(2);
    {
        float s[2][4][4];
        #pragma unroll
        for (int t = 0; t < 2; t++)
            #pragma unroll
            for (int j = 0; j < 4; j++)
                #pragma unroll
                for (int q = 0; q < 4; q++) s[t][j][q] = 0.f;
        s_tile(s, sm);
        soft_store(s);
    }

    for (int kt = 0; kt < 63; kt++) {
        if (kt < 62) { CP_WAIT1(); } else { CP_WAIT0(); }
        __syncthreads();
        if (kt + 3 < 64) issue_kv(kt + 3);
        const float* Kb = sm + ((kt + 1) & 3) * ASTAGE;
        const float* Vb = sm + (kt & 3) * ASTAGE + 32 * AK_STR;

        float s[2][4][4];
        #pragma unroll
        for (int t = 0; t < 2; t++)
            #pragma unroll
            for (int j = 0; j < 4; j++)
                #pragma unroll
                for (int q = 0; q < 4; q++) s[t][j][q] = 0.f;

        s_tile(s, Kb);
        pv_tile(Vb);
        soft_store(s);
    }
    pv_tile(sm + (63 & 3) * ASTAGE + 32 * AK_STR);

    #pragma unroll
    for (int i = 0; i < 4; i++) {
        lp[i] += __shfl_xor_sync(0xffffffffu, lp[i], 1);
        lp[i] += __shfl_xor_sync(0xffffffffu, lp[i], 2);
    }
    const float ssm = *ssm_ptr;
    const size_t ob = (size_t)b * S_ * H_ + h * 64;
    #pragma unroll
    for (int t = 0; t < 2; t++) {
        const float i0 = ssm / lp[2 * t], i1 = ssm / lp[2 * t + 1];
        const int r0 = s0 + prow + 16 * t;
        #pragma unroll
        for (int j = 0; j < 8; j++) {
            int cc = j * 8 + 2 * tig;
            float v0 = o[t][j][0] * i0, v1 = o[t][j][1] * i0;
            float v2 = o[t][j][2] * i1, v3 = o[t][j][3] * i1;
            __nv_bfloat16 h0 = __float2bfloat16_rn(v0), h1 = __float2bfloat16_rn(v1);
            __nv_bfloat16 h2 = __float2bfloat16_rn(v2), h3 = __float2bfloat16_rn(v3);
            *(uint32_t*)&out_hi[ob + (size_t)r0 * H_ + cc] = bfpack(h0, h1);
            *(uint32_t*)&out_lo[ob + (size_t)r0 * H_ + cc] =
                bfpack(__float2bfloat16_rn(v0 - __bfloat162float(h0)),
                       __float2bfloat16_rn(v1 - __bfloat162float(h1)));
            *(uint32_t*)&out_hi[ob + (size_t)(r0 + 8) * H_ + cc] = bfpack(h2, h3);
            *(uint32_t*)&out_lo[ob + (size_t)(r0 + 8) * H_ + cc] =
                bfpack(__float2bfloat16_rn(v2 - __bfloat162float(h2)),
                       __float2bfloat16_rn(v3 - __bfloat162float(h3)));
        }
    }
}

// ---------------------------------------------------------------------------
// Launch pipeline (graph-capturable, allocation-free)
// ---------------------------------------------------------------------------
extern "C" void kernel_launch(void* const* d_in, const int* in_sizes, int n_in,
                              void* d_out, int out_size)
{
    const float* hidden = (const float*)d_in[0];
    const float* w_qkv  = (const float*)d_in[1];
    const float* w_o    = (const float*)d_in[2];
    const float* s_sm   = (const float*)d_in[4];

    float* qkv;
    __nv_bfloat16 *hh, *hl, *wh, *wl, *ath, *atl;
    cudaGetSymbolAddress((void**)&qkv, g_qkv);
    cudaGetSymbolAddress((void**)&hh,  g_hh);
    cudaGetSymbolAddress((void**)&hl,  g_hl);
    cudaGetSymbolAddress((void**)&wh,  g_wh);
    cudaGetSymbolAddress((void**)&wl,  g_wl);
    cudaGetSymbolAddress((void**)&ath, g_ath);
    cudaGetSymbolAddress((void**)&atl, g_atl);

    cudaFuncSetAttribute(gemm_bf16x3<1>,
                         cudaFuncAttributeMaxDynamicSharedMemorySize, GBSMEM_BYTES);
    cudaFuncSetAttribute(gemm_bf16x3<0>,
                         cudaFuncAttributeMaxDynamicSharedMemorySize, GBSMEM_BYTES);
    cudaFuncSetAttribute(flash_attn_mma,
                         cudaFuncAttributeMaxDynamicSharedMemorySize, ATT_SMEM_BYTES);

    split_bf16<<<1024, 256>>>((const float4*)hidden, (uint2*)hh, (uint2*)hl,
                              (M_TOT * H_) / 4);
    tsplit_bf16<<<dim3((3 * H_) / 32, H_ / 32), dim3(32, 8)>>>(
        w_qkv, wh, wl, H_, 3 * H_);
    gemm_bf16x3<1><<<dim3((3 * H_) / 128, M_TOT / 128), 256, GBSMEM_BYTES>>>(
        hh, hl, wh, wl, qkv, M_TOT, 3 * H_, H_);
    flash_attn_mma<<<dim3(S_ / 128, B_ * NH_), 128, ATT_SMEM_BYTES>>>(
        qkv, ath, atl, s_sm);
    tsplit_bf16<<<dim3(H_ / 32, H_ / 32), dim3(32, 8)>>>(
        w_o, wh, wl, H_, H_);
    gemm_bf16x3<0><<<dim3(H_ / 128, M_TOT / 128), 256, GBSMEM_BYTES>>>(
        ath, atl, wh, wl, (float*)d_out, M_TOT, H_, H_);
}

// round 17
// speedup vs baseline: 1.1146x; 1.1146x over previous
#include <cuda_runtime.h>
#include <cuda_bf16.h>
#include <cstdint>

// Problem constants: B=2, S=2048, H=1024, NH=16, d=64
#define B_    2
#define S_    2048
#define H_    1024
#define NH_   16
#define DH_   64
#define M_TOT 4096

// ---------------- static device scratch (allocation-free) ----------------
__device__ float          g_qkv [M_TOT * 3 * H_];   // tf32-rounded
__device__ __nv_bfloat16  g_hh  [M_TOT * H_];
__device__ __nv_bfloat16  g_hl  [M_TOT * H_];
__device__ __nv_bfloat16  g_wh  [3 * H_ * H_];
__device__ __nv_bfloat16  g_wl  [3 * H_ * H_];
__device__ __nv_bfloat16  g_ath [M_TOT * H_];
__device__ __nv_bfloat16  g_atl [M_TOT * H_];

// ---------------- helpers ----------------
static __device__ __forceinline__ uint32_t smem_u32(const void* p) {
    uint32_t a;
    asm("{ .reg .u64 t; cvta.to.shared.u64 t, %1; cvt.u32.u64 %0, t; }"
        : "=r"(a) : "l"(p));
    return a;
}
static __device__ __forceinline__ uint32_t tf32_bits(float x) {
    uint32_t r; asm("cvt.rna.tf32.f32 %0, %1;" : "=r"(r) : "f"(x)); return r;
}
static __device__ __forceinline__ float tf32_rna(float x) {
    return __uint_as_float(tf32_bits(x));
}
static __device__ __forceinline__ float ex2f(float x) {
    float r; asm("ex2.approx.f32 %0, %1;" : "=f"(r) : "f"(x)); return r;
}
static __device__ __forceinline__ uint32_t f2u(float x) { return __float_as_uint(x); }
static __device__ __forceinline__ uint32_t bfpack(__nv_bfloat16 a, __nv_bfloat16 b) {
    return (uint32_t)__bfloat16_as_ushort(a) |
           ((uint32_t)__bfloat16_as_ushort(b) << 16);
}

#define CP16(dst, src) \
    asm volatile("cp.async.cg.shared.global [%0], [%1], 16;" :: "r"(dst), "l"(src))
#define CP_COMMIT() asm volatile("cp.async.commit_group;" ::: "memory")
#define CP_WAIT1()  asm volatile("cp.async.wait_group 1;" ::: "memory")
#define CP_WAIT0()  asm volatile("cp.async.wait_group 0;" ::: "memory")

#define LDSM4(r, addr)                                                        \
    asm volatile("ldmatrix.sync.aligned.m8n8.x4.shared.b16 {%0,%1,%2,%3}, [%4];" \
        : "=r"((r)[0]), "=r"((r)[1]), "=r"((r)[2]), "=r"((r)[3]) : "r"(addr))

// m16n8k8 tf32 mma (attention)
static __device__ __forceinline__ void mma8(float* c, const uint32_t* a,
                                            const uint32_t* b) {
    asm volatile(
        "mma.sync.aligned.m16n8k8.row.col.f32.tf32.tf32.f32 "
        "{%0,%1,%2,%3},{%4,%5,%6,%7},{%8,%9},{%0,%1,%2,%3};"
        : "+f"(c[0]), "+f"(c[1]), "+f"(c[2]), "+f"(c[3])
        : "r"(a[0]), "r"(a[1]), "r"(a[2]), "r"(a[3]), "r"(b[0]), "r"(b[1]));
}
// m16n8k16 bf16 mma (dense GEMMs)
static __device__ __forceinline__ void mma16(float* c, const uint32_t* a,
                                             const uint32_t* b) {
    asm volatile(
        "mma.sync.aligned.m16n8k16.row.col.f32.bf16.bf16.f32 "
        "{%0,%1,%2,%3},{%4,%5,%6,%7},{%8,%9},{%0,%1,%2,%3};"
        : "+f"(c[0]), "+f"(c[1]), "+f"(c[2]), "+f"(c[3])
        : "r"(a[0]), "r"(a[1]), "r"(a[2]), "r"(a[3]), "r"(b[0]), "r"(b[1]));
}

// ---------------------------------------------------------------------------
// Pre-pass 1: fp32 -> bf16 hi/lo split
// ---------------------------------------------------------------------------
__global__ void split_bf16(const float4* __restrict__ x, uint2* __restrict__ hi,
                           uint2* __restrict__ lo, int n4)
{
    for (int i = blockIdx.x * blockDim.x + threadIdx.x; i < n4;
         i += gridDim.x * blockDim.x) {
        float4 v = x[i];
        __nv_bfloat16 h0 = __float2bfloat16_rn(v.x);
        __nv_bfloat16 h1 = __float2bfloat16_rn(v.y);
        __nv_bfloat16 h2 = __float2bfloat16_rn(v.z);
        __nv_bfloat16 h3 = __float2bfloat16_rn(v.w);
        __nv_bfloat16 l0 = __float2bfloat16_rn(v.x - __bfloat162float(h0));
        __nv_bfloat16 l1 = __float2bfloat16_rn(v.y - __bfloat162float(h1));
        __nv_bfloat16 l2 = __float2bfloat16_rn(v.z - __bfloat162float(h2));
        __nv_bfloat16 l3 = __float2bfloat16_rn(v.w - __bfloat162float(h3));
        hi[i] = make_uint2(bfpack(h0, h1), bfpack(h2, h3));
        lo[i] = make_uint2(bfpack(l0, l1), bfpack(l2, l3));
    }
}

// ---------------------------------------------------------------------------
// Pre-pass 2: W[K][N] -> W^T hi/lo [N][K] bf16 (transpose + split)
// ---------------------------------------------------------------------------
__global__ void tsplit_bf16(const float* __restrict__ W,
                            __nv_bfloat16* __restrict__ bth,
                            __nv_bfloat16* __restrict__ btl, int K, int N)
{
    __shared__ float t[32][33];
    const int tx = threadIdx.x, ty = threadIdx.y;
    const int n0 = blockIdx.x * 32, k0 = blockIdx.y * 32;
    #pragma unroll
    for (int i = 0; i < 4; i++)
        t[ty + i * 8][tx] = W[(size_t)(k0 + ty + i * 8) * N + n0 + tx];
    __syncthreads();
    #pragma unroll
    for (int i = 0; i < 4; i++) {
        float v = t[tx][ty + i * 8];
        __nv_bfloat16 h = __float2bfloat16_rn(v);
        __nv_bfloat16 l = __float2bfloat16_rn(v - __bfloat162float(h));
        size_t o = (size_t)(n0 + ty + i * 8) * K + k0 + tx;
        bth[o] = h; btl[o] = l;
    }
}

// ---------------------------------------------------------------------------
// bf16x3 GEMM: CTA 128x128, 4 warps (64x64 tiles), K-stage 32, 3-stage ring
// with SINGLE barrier per stage + issue overlapped with compute. Pad-free
// XOR chunk swizzle (c ^= (row>>1)&3) keeps cp.async + ldmatrix conflict-free.
// ---------------------------------------------------------------------------
#define GBW     16                       // u32 words per row (no pad; swizzled)
#define GBARR   (128 * GBW)              // 2048 words (8 KB) per matrix/stage
#define GBSTAGE (4 * GBARR)              // Ah, Al, Bh, Bl = 32 KB per stage
#define GBSMEM_BYTES (3 * GBSTAGE * 4)   // 98304 (3 ring stages)

template <int ROUND>
__global__ __launch_bounds__(128, 2)
void gemm_bf16x3(const __nv_bfloat16* __restrict__ Ah,
                 const __nv_bfloat16* __restrict__ Al,
                 const __nv_bfloat16* __restrict__ Bh,
                 const __nv_bfloat16* __restrict__ Bl,
                 float* __restrict__ C, int M, int N, int K)
{
    extern __shared__ uint32_t smw[];
    const uint32_t sbase = smem_u32(smw);
    const int tid = threadIdx.x, lane = tid & 31, wid = tid >> 5;
    const int g = lane >> 2, tig = lane & 3;
    const int wm = wid & 1, wn = wid >> 1;       // 2m x 2n, warp 64x64
    const int m0 = blockIdx.y * 128, n0 = blockIdx.x * 128;
    const int nst = K / 32;

    float acc[4][8][4];
    #pragma unroll
    for (int i = 0; i < 4; i++)
        #pragma unroll
        for (int j = 0; j < 8; j++)
            #pragma unroll
            for (int q = 0; q < 4; q++) acc[i][j][q] = 0.f;

    auto issue = [&](int s) {
        const int buf = s % 3, k0 = s * 32;
        const uint32_t sb = sbase + (uint32_t)buf * (GBSTAGE * 4);
        #pragma unroll
        for (int i = 0; i < 4; i++) {
            int l = i * 128 + tid;                // 512 16B-chunks per matrix
            int r = l >> 2, c = l & 3;
            int cp = c ^ ((r >> 1) & 3);          // XOR swizzle
            uint32_t off = (uint32_t)(r * 64 + cp * 16);
            size_t ga = (size_t)(m0 + r) * K + k0 + c * 8;
            size_t gb = (size_t)(n0 + r) * K + k0 + c * 8;
            CP16(sb + off,                 &Ah[ga]);
            CP16(sb + GBARR * 4 + off,     &Al[ga]);
            CP16(sb + 2 * GBARR * 4 + off, &Bh[gb]);
            CP16(sb + 3 * GBARR * 4 + off, &Bl[gb]);
        }
        CP_COMMIT();
    };
    issue(0); issue(1);

    // ldmatrix per-thread bases (row part) + swizzle constants
    const int rowA = (lane & 7) + 8 * ((lane >> 3) & 1);
    const int c0A  = lane >> 4;                   // chunk 0/1
    const int swzA = (rowA >> 1) & 3;             // invariant across m16 tiles
    const int rowB = (lane & 7) + 8 * (lane >> 4);
    const int c0B  = (lane >> 3) & 1;
    const int swzB = (rowB >> 1) & 3;
    const uint32_t rbA = (uint32_t)(wm * 64 + rowA) * 64;
    const uint32_t rbB = (uint32_t)(wn * 64 + rowB) * 64;

    for (int s = 0; s < nst; s++) {
        if (s + 1 < nst) { CP_WAIT1(); } else { CP_WAIT0(); }
        __syncthreads();              // publish stage s; fence stage s-1 reads
        if (s + 2 < nst) issue(s + 2);   // overwrites (s+2)%3 = (s-1)%3: safe

        const uint32_t bb = sbase + (uint32_t)(s % 3) * (GBSTAGE * 4);
        const uint32_t aHb = bb + rbA;
        const uint32_t aLb = aHb + GBARR * 4;
        const uint32_t bHb = bb + 2 * GBARR * 4 + rbB;
        const uint32_t bLb = bHb + GBARR * 4;

        #pragma unroll
        for (int s8 = 0; s8 < 2; s8++) {
            const uint32_t ca = (uint32_t)(((c0A + 2 * s8) ^ swzA) * 16);
            const uint32_t cb = (uint32_t)(((c0B + 2 * s8) ^ swzB) * 16);
            uint32_t ah[4][4], al[4][4];
            #pragma unroll
            for (int i = 0; i < 4; i++) {
                LDSM4(ah[i], aHb + (uint32_t)i * 1024 + ca);   // 16 rows * 64B
                LDSM4(al[i], aLb + (uint32_t)i * 1024 + ca);
            }
            #pragma unroll
            for (int jp = 0; jp < 4; jp++) {
                uint32_t bh[4], bl[4];
                LDSM4(bh, bHb + (uint32_t)jp * 1024 + cb);
                LDSM4(bl, bLb + (uint32_t)jp * 1024 + cb);
                // term-grouped: each acc reused at distance 8 MMAs
                #pragma unroll
                for (int i = 0; i < 4; i++) {
                    mma16(acc[i][2 * jp],     ah[i], bh);
                    mma16(acc[i][2 * jp + 1], ah[i], bh + 2);
                }
                #pragma unroll
                for (int i = 0; i < 4; i++) {
                    mma16(acc[i][2 * jp],     ah[i], bl);
                    mma16(acc[i][2 * jp + 1], ah[i], bl + 2);
                }
                #pragma unroll
                for (int i = 0; i < 4; i++) {
                    mma16(acc[i][2 * jp],     al[i], bh);
                    mma16(acc[i][2 * jp + 1], al[i], bh + 2);
                }
            }
        }
    }

    #pragma unroll
    for (int i = 0; i < 4; i++) {
        int r0 = m0 + wm * 64 + i * 16 + g;
        #pragma unroll
        for (int j = 0; j < 8; j++) {
            int cn = n0 + wn * 64 + j * 8 + 2 * tig;
            float4 v = make_float4(acc[i][j][0], acc[i][j][1],
                                   acc[i][j][2], acc[i][j][3]);
            if (ROUND) {
                v.x = tf32_rna(v.x); v.y = tf32_rna(v.y);
                v.z = tf32_rna(v.z); v.w = tf32_rna(v.w);
            }
            *(float2*)&C[(size_t)r0 * N + cn] = make_float2(v.x, v.y);
            *(float2*)&C[(size_t)(r0 + 8) * N + cn] = make_float2(v.z, v.w);
        }
    }
}

// ---------------------------------------------------------------------------
// Flash attention (byte-identical to round 14 best): software-pipelined
// S(kt+1)+PV(kt), 4-stage K/V ring, no-max softmax, Q in regs, 2 CTAs/SM.
// ---------------------------------------------------------------------------
#define AQ_STR 68
#define AK_STR 68
#define AV_STR 72
#define AP_STR 36
#define ASTAGE (32 * AK_STR + 32 * AV_STR)       // 4480 floats per ring stage
#define OFF_P  (4 * ASTAGE)                      // 17920
#define ATT_SMEM_FLOATS (OFF_P + 128 * AP_STR)   // 22528
#define ATT_SMEM_BYTES  (ATT_SMEM_FLOATS * 4)    // 90112

__global__ __launch_bounds__(128, 2)
void flash_attn_mma(const float* __restrict__ qkv,
                    __nv_bfloat16* __restrict__ out_hi,
                    __nv_bfloat16* __restrict__ out_lo,
                    const float* __restrict__ ssm_ptr)
{
    extern __shared__ float sm[];
    const uint32_t sbase = smem_u32(sm);
    const int tid = threadIdx.x, lane = tid & 31, wid = tid >> 5;
    const int g = lane >> 2, tig = lane & 3;
    const int qt = blockIdx.x, bh = blockIdx.y;
    const int b = bh >> 4, h = bh & 15;
    const int s0 = qt * 128;

    const float* qbase = qkv + (size_t)b * S_ * 3072 + h * 64;
    const float* kbase = qbase + 1024;
    const float* vbase = qbase + 2048;

    const int prow = 32 * wid + g;

    const float QSC = 0.125f * 1.4426950408889634f;
    #pragma unroll
    for (int it = 0; it < 16; it++) {
        int lin = it * 128 + tid;
        int r = lin >> 4, c = (lin & 15) * 4;
        float4 v = *(const float4*)&qbase[(size_t)(s0 + r) * 3072 + c];
        v.x = tf32_rna(v.x * QSC); v.y = tf32_rna(v.y * QSC);
        v.z = tf32_rna(v.z * QSC); v.w = tf32_rna(v.w * QSC);
        *(float4*)&sm[r * AQ_STR + c] = v;
    }
    __syncthreads();
    uint32_t qreg[2][8][4];
    #pragma unroll
    for (int t = 0; t < 2; t++) {
        const int rr = prow + 16 * t;
        #pragma unroll
        for (int k8 = 0; k8 < 8; k8++) {
            const int kc = k8 * 8;
            qreg[t][k8][0] = f2u(sm[rr * AQ_STR + kc + tig]);
            qreg[t][k8][1] = f2u(sm[(rr + 8) * AQ_STR + kc + tig]);
            qreg[t][k8][2] = f2u(sm[rr * AQ_STR + kc + tig + 4]);
            qreg[t][k8][3] = f2u(sm[(rr + 8) * AQ_STR + kc + tig + 4]);
        }
    }
    __syncthreads();

    auto issue_kv = [&](int kt) {
        const int buf = kt & 3, j0 = kt * 32;
        const uint32_t kdst = sbase + (uint32_t)(buf * ASTAGE) * 4;
        const uint32_t vdst = kdst + (uint32_t)(32 * AK_STR) * 4;
        #pragma unroll
        for (int i = 0; i < 4; i++) {
            int l = i * 128 + tid;
            int r = l >> 4, ch = (l & 15) * 4;
            CP16(kdst + (uint32_t)(r * AK_STR + ch) * 4,
                 &kbase[(size_t)(j0 + r) * 3072 + ch]);
            CP16(vdst + (uint32_t)(r * AV_STR + ch) * 4,
                 &vbase[(size_t)(j0 + r) * 3072 + ch]);
        }
        CP_COMMIT();
    };

    float lp[4] = {0.f, 0.f, 0.f, 0.f};
    float o[2][8][4];
    #pragma unroll
    for (int t = 0; t < 2; t++)
        #pragma unroll
        for (int j = 0; j < 8; j++)
            #pragma unroll
            for (int q = 0; q < 4; q++) o[t][j][q] = 0.f;

    auto s_tile = [&](float s[2][4][4], const float* Kb) {
        #pragma unroll
        for (int k8 = 0; k8 < 8; k8++) {
            const int kc = k8 * 8;
            #pragma unroll
            for (int j = 0; j < 4; j++) {
                uint32_t bb[2];
                bb[0] = f2u(Kb[(8 * j + g) * AK_STR + kc + tig]);
                bb[1] = f2u(Kb[(8 * j + g) * AK_STR + kc + tig + 4]);
                mma8(s[0][j], qreg[0][k8], bb);
                mma8(s[1][j], qreg[1][k8], bb);
            }
        }
    };
    auto soft_store = [&](float s[2][4][4]) {
        #pragma unroll
        for (int t = 0; t < 2; t++) {
            const int rr = prow + 16 * t;
            #pragma unroll
            for (int j = 0; j < 4; j++) {
                float p0 = ex2f(s[t][j][0]), p1 = ex2f(s[t][j][1]);
                float p2 = ex2f(s[t][j][2]), p3 = ex2f(s[t][j][3]);
                lp[2 * t]     += p0 + p1;
                lp[2 * t + 1] += p2 + p3;
                int cc = j * 8 + 2 * tig;
                *(float2*)&sm[OFF_P + rr * AP_STR + cc] =
                    make_float2(tf32_rna(p0), tf32_rna(p1));
                *(float2*)&sm[OFF_P + (rr + 8) * AP_STR + cc] =
                    make_float2(tf32_rna(p2), tf32_rna(p3));
            }
        }
        __syncwarp();
    };
    auto pv_tile = [&](const float* Vb) {
        #pragma unroll
        for (int k8 = 0; k8 < 4; k8++) {
            const int kc = k8 * 8;
            uint32_t pa[2][4];
            #pragma unroll
            for (int t = 0; t < 2; t++) {
                int rr = prow + 16 * t;
                pa[t][0] = f2u(sm[OFF_P + rr * AP_STR + kc + tig]);
                pa[t][1] = f2u(sm[OFF_P + (rr + 8) * AP_STR + kc + tig]);
                pa[t][2] = f2u(sm[OFF_P + rr * AP_STR + kc + tig + 4]);
                pa[t][3] = f2u(sm[OFF_P + (rr + 8) * AP_STR + kc + tig + 4]);
            }
            #pragma unroll
            for (int j = 0; j < 8; j++) {
                uint32_t bb[2];
                bb[0] = f2u(Vb[(kc + tig) * AV_STR + j * 8 + g]);
                bb[1] = f2u(Vb[(kc + tig + 4) * AV_STR + j * 8 + g]);
                mma8(o[0][j], pa[0], bb);
                mma8(o[1][j], pa[1], bb);
            }
        }
    };

    issue_kv(0); issue_kv(1);
    CP_WAIT1();
    __syncthreads();
    issue_kv(2);
    {
        float s[2][4][4];
        #pragma unroll
        for (int t = 0; t < 2; t++)
            #pragma unroll
            for (int j = 0; j < 4; j++)
                #pragma unroll
                for (int q = 0; q < 4; q++) s[t][j][q] = 0.f;
        s_tile(s, sm);
        soft_store(s);
    }

    for (int kt = 0; kt < 63; kt++) {
        if (kt < 62) { CP_WAIT1(); } else { CP_WAIT0(); }
        __syncthreads();
        if (kt + 3 < 64) issue_kv(kt + 3);
        const float* Kb = sm + ((kt + 1) & 3) * ASTAGE;
        const float* Vb = sm + (kt & 3) * ASTAGE + 32 * AK_STR;

        float s[2][4][4];
        #pragma unroll
        for (int t = 0; t < 2; t++)
            #pragma unroll
            for (int j = 0; j < 4; j++)
                #pragma unroll
                for (int q = 0; q < 4; q++) s[t][j][q] = 0.f;

        s_tile(s, Kb);
        pv_tile(Vb);
        soft_store(s);
    }
    pv_tile(sm + (63 & 3) * ASTAGE + 32 * AK_STR);

    #pragma unroll
    for (int i = 0; i < 4; i++) {
        lp[i] += __shfl_xor_sync(0xffffffffu, lp[i], 1);
        lp[i] += __shfl_xor_sync(0xffffffffu, lp[i], 2);
    }
    const float ssm = *ssm_ptr;
    const size_t ob = (size_t)b * S_ * H_ + h * 64;
    #pragma unroll
    for (int t = 0; t < 2; t++) {
        const float i0 = ssm / lp[2 * t], i1 = ssm / lp[2 * t + 1];
        const int r0 = s0 + prow + 16 * t;
        #pragma unroll
        for (int j = 0; j < 8; j++) {
            int cc = j * 8 + 2 * tig;
            float v0 = o[t][j][0] * i0, v1 = o[t][j][1] * i0;
            float v2 = o[t][j][2] * i1, v3 = o[t][j][3] * i1;
            __nv_bfloat16 h0 = __float2bfloat16_rn(v0), h1 = __float2bfloat16_rn(v1);
            __nv_bfloat16 h2 = __float2bfloat16_rn(v2), h3 = __float2bfloat16_rn(v3);
            *(uint32_t*)&out_hi[ob + (size_t)r0 * H_ + cc] = bfpack(h0, h1);
            *(uint32_t*)&out_lo[ob + (size_t)r0 * H_ + cc] =
                bfpack(__float2bfloat16_rn(v0 - __bfloat162float(h0)),
                       __float2bfloat16_rn(v1 - __bfloat162float(h1)));
            *(uint32_t*)&out_hi[ob + (size_t)(r0 + 8) * H_ + cc] = bfpack(h2, h3);
            *(uint32_t*)&out_lo[ob + (size_t)(r0 + 8) * H_ + cc] =
                bfpack(__float2bfloat16_rn(v2 - __bfloat162float(h2)),
                       __float2bfloat16_rn(v3 - __bfloat162float(h3)));
        }
    }
}

// ---------------------------------------------------------------------------
// Launch pipeline (graph-capturable, allocation-free)
// ---------------------------------------------------------------------------
extern "C" void kernel_launch(void* const* d_in, const int* in_sizes, int n_in,
                              void* d_out, int out_size)
{
    const float* hidden = (const float*)d_in[0];
    const float* w_qkv  = (const float*)d_in[1];
    const float* w_o    = (const float*)d_in[2];
    const float* s_sm   = (const float*)d_in[4];

    float* qkv;
    __nv_bfloat16 *hh, *hl, *wh, *wl, *ath, *atl;
    cudaGetSymbolAddress((void**)&qkv, g_qkv);
    cudaGetSymbolAddress((void**)&hh,  g_hh);
    cudaGetSymbolAddress((void**)&hl,  g_hl);
    cudaGetSymbolAddress((void**)&wh,  g_wh);
    cudaGetSymbolAddress((void**)&wl,  g_wl);
    cudaGetSymbolAddress((void**)&ath, g_ath);
    cudaGetSymbolAddress((void**)&atl, g_atl);

    cudaFuncSetAttribute(gemm_bf16x3<1>,
                         cudaFuncAttributeMaxDynamicSharedMemorySize, GBSMEM_BYTES);
    cudaFuncSetAttribute(gemm_bf16x3<0>,
                         cudaFuncAttributeMaxDynamicSharedMemorySize, GBSMEM_BYTES);
    cudaFuncSetAttribute(flash_attn_mma,
                         cudaFuncAttributeMaxDynamicSharedMemorySize, ATT_SMEM_BYTES);

    split_bf16<<<1024, 256>>>((const float4*)hidden, (uint2*)hh, (uint2*)hl,
                              (M_TOT * H_) / 4);
    tsplit_bf16<<<dim3((3 * H_) / 32, H_ / 32), dim3(32, 8)>>>(
        w_qkv, wh, wl, H_, 3 * H_);
    gemm_bf16x3<1><<<dim3((3 * H_) / 128, M_TOT / 128), 128, GBSMEM_BYTES>>>(
        hh, hl, wh, wl, qkv, M_TOT, 3 * H_, H_);
    flash_attn_mma<<<dim3(S_ / 128, B_ * NH_), 128, ATT_SMEM_BYTES>>>(
        qkv, ath, atl, s_sm);
    tsplit_bf16<<<dim3(H_ / 32, H_ / 32), dim3(32, 8)>>>(
        w_o, wh, wl, H_, H_);
    gemm_bf16x3<0><<<dim3(H_ / 128, M_TOT / 128), 128, GBSMEM_BYTES>>>(
        ath, atl, wh, wl, (float*)d_out, M_TOT, H_, H_);
}